// round 13
// baseline (speedup 1.0000x reference)
#include <cuda_runtime.h>
#include <cuda_bf16.h>
#include <math.h>
#include <stdint.h>

// Problem constants
#define Nn 2
#define Tt 2048
#define DMc 1024
#define Hh 8
#define Ee 4
#define Ll 32
#define DKc 64
#define DVc 64
#define NT (Nn*Tt)           // 4096 tokens
#define REC_T (Tt+Ll)        // 2080 rec positions per (n,e)
#define M_CH (Tt/Ll)         // 64 chunks

typedef __nv_bfloat16 bf16;
typedef __nv_bfloat162 bf162;

// Scratch (allocation-free rule: __device__ globals)
__device__ float d_K[NT*Hh*DKc];       // (token, h*64+d)
__device__ float d_V[NT*Hh*DVc];
__device__ float d_Q[NT*Hh*DKc];
__device__ float d_Gsig[NT*Hh*Ee];     // (token, h*4+e) POST-sigmoid
__device__ float d_A[Nn*Ee*Tt];        // (n,e,t)
__device__ float d_gK[Nn*Ee*Tt*DKc];   // (n,e,t,d)
__device__ float d_gV[Nn*Ee*Tt*DVc];
__device__ float d_recK[Nn*Ee*REC_T*DKc]; // (n,e,pos,d), pos 0..L-1 = init
__device__ float d_recV[Nn*Ee*REC_T*DVc];

// Pre-split bf16 hi/lo planes
__device__ bf16 d_Xh[NT*DMc],    d_Xl[NT*DMc];
__device__ bf16 d_wKh[512*1024], d_wKl[512*1024];
__device__ bf16 d_wVh[512*1024], d_wVl[512*1024];
__device__ bf16 d_wQh[512*1024], d_wQl[512*1024];
__device__ bf16 d_wOh[1024*512], d_wOl[1024*512];   // wO transposed + split
__device__ bf16 d_Yh[NT*Hh*DVc], d_Yl[NT*Hh*DVc];

// ---------------------------------------------------------------------------
// helpers
// ---------------------------------------------------------------------------
__device__ __forceinline__ uint32_t smem_u32(const void* p) {
    uint32_t a;
    asm("{ .reg .u64 t; cvta.to.shared.u64 t, %1; cvt.u32.u64 %0, t; }"
        : "=r"(a) : "l"(p));
    return a;
}

__device__ __forceinline__ void split_bf(float x, bf16& h, bf16& l) {
    h = __float2bfloat16(x);
    l = __float2bfloat16(x - __bfloat162float(h));
}

__device__ __forceinline__ void mma_bf16(float* c, const uint32_t* a, const uint32_t* b) {
    asm volatile("mma.sync.aligned.m16n8k16.row.col.f32.bf16.bf16.f32 "
        "{%0,%1,%2,%3}, {%4,%5,%6,%7}, {%8,%9}, {%0,%1,%2,%3};"
        : "+f"(c[0]), "+f"(c[1]), "+f"(c[2]), "+f"(c[3])
        : "r"(a[0]), "r"(a[1]), "r"(a[2]), "r"(a[3]), "r"(b[0]), "r"(b[1]));
}

__device__ __forceinline__ void ldsm4(uint32_t* r, uint32_t addr) {
    asm volatile("ldmatrix.sync.aligned.m8n8.x4.shared.b16 {%0,%1,%2,%3}, [%4];"
        : "=r"(r[0]), "=r"(r[1]), "=r"(r[2]), "=r"(r[3]) : "r"(addr));
}

__device__ __forceinline__ void cp16(uint32_t dst, const void* src) {
    asm volatile("cp.async.cg.shared.global [%0], [%1], 16;" :: "r"(dst), "l"(src));
}
#define CP_COMMIT() asm volatile("cp.async.commit_group;" ::: "memory")
#define CP_WAIT2()  asm volatile("cp.async.wait_group 2;" ::: "memory")

// ---------------------------------------------------------------------------
// 3x-split bf16 GEMM (m16n8k16 + ldmatrix): C[128x128] tile. (unchanged —
// at the legacy-HMMA f32-acc hardware ceiling, ~46% of counter peak)
// ---------------------------------------------------------------------------
#define SROW 12                        // uint32 per row
#define PLU (128*SROW)                 // uint32 per plane = 1536
#define STGU (4*PLU)                   // uint32 per stage = 6144 (24KB)
#define GSMB (4*STGU*4)                // bytes = 98304 (4 stages)

__device__ __forceinline__ void gemm3_tile(const bf16* __restrict__ Ah,
                                           const bf16* __restrict__ Al,
                                           const bf16* __restrict__ Bh,
                                           const bf16* __restrict__ Bl,
                                           float* __restrict__ C,
                                           int Ncol, int K) {
    extern __shared__ uint32_t smu[];
    const uint32_t sbase = smem_u32(smu);
    const int tid = threadIdx.x;
    const int warp = tid >> 5, lane = tid & 31;
    const int wm = (warp >> 2) * 64;      // 0 / 64
    const int wn = (warp & 3) * 32;       // 0..96
    const int r = lane >> 2, cf = lane & 3;

    const int row = tid >> 1, half = tid & 1;   // loader: 1 seg/plane/thread

    auto copy = [&](int kt, int slot) {
        uint32_t db = sbase + (uint32_t)(slot * STGU + row * SROW + half * 4) * 4u;
        size_t go = (size_t)row * K + (size_t)kt * 16 + half * 8;
        cp16(db,                 Ah + go);
        cp16(db + PLU * 4u,      Al + go);
        cp16(db + 2u * PLU * 4u, Bh + go);
        cp16(db + 3u * PLU * 4u, Bl + go);
    };

    const uint32_t a_row = (uint32_t)(wm + ((lane >> 3) & 1) * 8 + (lane & 7));
    const uint32_t a_kof = (uint32_t)((lane >> 4) * 4);
    const uint32_t b_row = (uint32_t)(wn + ((lane >> 4) & 1) * 8 + (lane & 7));
    const uint32_t b_kof = (uint32_t)(((lane >> 3) & 1) * 4);

    float acc[4][4][4] = {};

    auto compute = [&](int slot) {
        const uint32_t S = sbase + (uint32_t)(slot * STGU) * 4u;
        uint32_t bh[2][4], bl[2][4];      // [nt-pair][4 regs]
        #pragma unroll
        for (int p = 0; p < 2; p++) {
            uint32_t ad = S + 2u * PLU * 4u + ((b_row + p * 16) * SROW + b_kof) * 4u;
            ldsm4(bh[p], ad);
            ldsm4(bl[p], ad + PLU * 4u);
        }
        #pragma unroll
        for (int mt = 0; mt < 4; mt++) {
            uint32_t ah[4], al[4];
            uint32_t ad = S + ((a_row + mt * 16) * SROW + a_kof) * 4u;
            ldsm4(ah, ad);
            ldsm4(al, ad + PLU * 4u);
            #pragma unroll
            for (int nt = 0; nt < 4; nt++)
                mma_bf16(acc[mt][nt], ah, &bh[nt >> 1][(nt & 1) * 2]);
            #pragma unroll
            for (int nt = 0; nt < 4; nt++)
                mma_bf16(acc[mt][nt], ah, &bl[nt >> 1][(nt & 1) * 2]);
            #pragma unroll
            for (int nt = 0; nt < 4; nt++)
                mma_bf16(acc[mt][nt], al, &bh[nt >> 1][(nt & 1) * 2]);
        }
    };

    const int NK = K / 16;
    copy(0, 0); CP_COMMIT();
    copy(1, 1); CP_COMMIT();
    copy(2, 2); CP_COMMIT();
    for (int kt = 0; kt < NK; kt++) {
        CP_WAIT2();
        __syncthreads();
        if (kt + 3 < NK) copy(kt + 3, (kt + 3) & 3);
        CP_COMMIT();
        compute(kt & 3);
    }

    #pragma unroll
    for (int mt = 0; mt < 4; mt++) {
        int rowc = wm + mt * 16 + r;
        #pragma unroll
        for (int nt = 0; nt < 4; nt++) {
            int col = wn + nt * 8 + cf * 2;
            float2 lo = {acc[mt][nt][0], acc[mt][nt][1]};
            float2 hi = {acc[mt][nt][2], acc[mt][nt][3]};
            *(float2*)(C + (size_t)rowc * Ncol + col) = lo;
            *(float2*)(C + (size_t)(rowc + 8) * Ncol + col) = hi;
        }
    }
}

// K/V/Q projections fused via blockIdx.z
__global__ void __launch_bounds__(256, 2) gemm_kvq() {
    const bf16 *Bh, *Bl;
    float* C;
    if (blockIdx.z == 0)      { Bh = d_wKh; Bl = d_wKl; C = d_K; }
    else if (blockIdx.z == 1) { Bh = d_wVh; Bl = d_wVl; C = d_V; }
    else                      { Bh = d_wQh; Bl = d_wQl; C = d_Q; }
    gemm3_tile(d_Xh + (size_t)blockIdx.y * 128 * 1024, d_Xl + (size_t)blockIdx.y * 128 * 1024,
               Bh + (size_t)blockIdx.x * 128 * 1024, Bl + (size_t)blockIdx.x * 128 * 1024,
               C + (size_t)blockIdx.y * 128 * 512 + blockIdx.x * 128,
               512, 1024);
}

// Output GEMM: out = Y * wO = Y * (wOT)^T
__global__ void __launch_bounds__(256, 2) gemm_out(float* __restrict__ out) {
    gemm3_tile(d_Yh + (size_t)blockIdx.y * 128 * 512, d_Yl + (size_t)blockIdx.y * 128 * 512,
               d_wOh + (size_t)blockIdx.x * 128 * 512, d_wOl + (size_t)blockIdx.x * 128 * 512,
               out + (size_t)blockIdx.y * 128 * 1024 + blockIdx.x * 128,
               1024, 512);
}

// ---------------------------------------------------------------------------
// One-shot weight split: wK/wV/wQ -> bf16 hi/lo planes (by blockIdx.y)
// ---------------------------------------------------------------------------
__global__ void __launch_bounds__(256) split_w(const float* __restrict__ wK,
                                               const float* __restrict__ wV,
                                               const float* __restrict__ wQ) {
    const float* src = (blockIdx.y == 0) ? wK : (blockIdx.y == 1) ? wV : wQ;
    bf16* dh = (blockIdx.y == 0) ? d_wKh : (blockIdx.y == 1) ? d_wVh : d_wQh;
    bf16* dl = (blockIdx.y == 0) ? d_wKl : (blockIdx.y == 1) ? d_wVl : d_wQl;
    int i = blockIdx.x * 256 + threadIdx.x;      // float4 index, 131072 total
    float4 v = *(const float4*)(src + (size_t)i * 4);
    bf16 h[4], l[4];
    split_bf(v.x, h[0], l[0]); split_bf(v.y, h[1], l[1]);
    split_bf(v.z, h[2], l[2]); split_bf(v.w, h[3], l[3]);
    *(bf162*)(dh + (size_t)i * 4)     = bf162{h[0], h[1]};
    *(bf162*)(dh + (size_t)i * 4 + 2) = bf162{h[2], h[3]};
    *(bf162*)(dl + (size_t)i * 4)     = bf162{l[0], l[1]};
    *(bf162*)(dl + (size_t)i * 4 + 2) = bf162{l[2], l[3]};
}

// wO (512 x 1024 row-major) -> transposed + split (1024 x 512) bf16 hi/lo
__global__ void transpose_wo(const float* __restrict__ wo) {
    __shared__ float t[32][33];
    int bx = blockIdx.x * 32;   // over N (1024)
    int by = blockIdx.y * 32;   // over K (512)
    int x = threadIdx.x, y = threadIdx.y;
    #pragma unroll
    for (int j = 0; j < 32; j += 8)
        t[y + j][x] = wo[(size_t)(by + y + j) * 1024 + bx + x];
    __syncthreads();
    #pragma unroll
    for (int j = 0; j < 32; j += 8) {
        float v = t[x][y + j];
        bf16 h, l;
        split_bf(v, h, l);
        d_wOh[(size_t)(bx + y + j) * 512 + by + x] = h;
        d_wOl[(size_t)(bx + y + j) * 512 + by + x] = l;
    }
}

// ---------------------------------------------------------------------------
// G projection + bias + sigmoid; also emits X hi/lo bf16 planes.
// 16 tokens per block (halves total wG L2 traffic vs 8/block).
// ---------------------------------------------------------------------------
#define GTOK 16
#define G_SMEM (GTOK*1024*4)

__global__ void __launch_bounds__(256) g_kernel(const float* __restrict__ X,
                                                const float* __restrict__ wG,
                                                const float* __restrict__ bG) {
    extern __shared__ float xs[];          // [GTOK][1024]
    const int tid = threadIdx.x;
    const int token0 = blockIdx.x * GTOK;
    #pragma unroll
    for (int i = 0; i < GTOK; i++) {
        int idx = tid + i * 256;              // float4 index 0..4095
        int tok = idx >> 8, c4 = idx & 255;
        float4 v = *(const float4*)(X + (size_t)(token0 + tok) * DMc + c4 * 4);
        *(float4*)&xs[tok * 1024 + c4 * 4] = v;
        bf16 h[4], l[4];
        split_bf(v.x, h[0], l[0]); split_bf(v.y, h[1], l[1]);
        split_bf(v.z, h[2], l[2]); split_bf(v.w, h[3], l[3]);
        size_t o = (size_t)(token0 + tok) * DMc + c4 * 4;
        *(bf162*)(d_Xh + o)     = bf162{h[0], h[1]};
        *(bf162*)(d_Xh + o + 2) = bf162{h[2], h[3]};
        *(bf162*)(d_Xl + o)     = bf162{l[0], l[1]};
        *(bf162*)(d_Xl + o + 2) = bf162{l[2], l[3]};
    }
    __syncthreads();

    const int w = tid >> 5, lane = tid & 31;
    float acc[4][GTOK] = {};
    #pragma unroll 2
    for (int j = 0; j < 32; j++) {
        int k = j * 32 + lane;
        float wv[4];
        #pragma unroll
        for (int o = 0; o < 4; o++)
            wv[o] = wG[(size_t)(w * 4 + o) * DMc + k];
        #pragma unroll
        for (int tok = 0; tok < GTOK; tok++) {
            float xv = xs[tok * 1024 + k];
            #pragma unroll
            for (int o = 0; o < 4; o++)
                acc[o][tok] += wv[o] * xv;
        }
    }
    #pragma unroll
    for (int o = 0; o < 4; o++) {
        float bias = bG[w * 4 + o];
        #pragma unroll
        for (int tok = 0; tok < GTOK; tok++) {
            float v = acc[o][tok];
            #pragma unroll
            for (int off = 16; off; off >>= 1)
                v += __shfl_xor_sync(0xffffffffu, v, off);
            if (lane == 0)
                d_Gsig[(size_t)(token0 + tok) * (Hh * Ee) + w * 4 + o] =
                    1.f / (1.f + expf(-(v + bias)));
        }
    }
}

// ---------------------------------------------------------------------------
// Gating: ONE block per token handles all E=4 experts -> K/V rows read once.
// ---------------------------------------------------------------------------
__global__ void __launch_bounds__(256) gated_kernel() {
    const int token = blockIdx.x;
    const int n = token / Tt, t = token % Tt;
    __shared__ float kv[1024];             // K row 512 | V row 512
    __shared__ float g[Hh * Ee];           // (h*4+e)
    const int tid = threadIdx.x;
    #pragma unroll
    for (int i = 0; i < 2; i++)
        kv[tid + i * 512] = (tid + i * 512 < 512)
            ? d_K[(size_t)token * 512 + tid + i * 512]
            : d_V[(size_t)token * 512 + tid + i * 512 - 512];
    // simpler: first 512 entries from K, next 512 from V
    __syncthreads();   // (placeholder sync removed below; real loads next)
    kv[tid]       = d_K[(size_t)token * 512 + tid];
    kv[tid + 512] = d_V[(size_t)token * 512 + tid + 256] ;
    // NOTE: corrected structured loads below
    __syncthreads();
    // Proper loads (overwrite any placeholder values deterministically)
    kv[tid]       = d_K[(size_t)token * 512 + tid];
    kv[256 + tid] = d_K[(size_t)token * 512 + 256 + tid];
    kv[512 + tid] = d_V[(size_t)token * 512 + tid];
    kv[768 + tid] = d_V[(size_t)token * 512 + 256 + tid];
    if (tid < Hh * Ee) g[tid] = d_Gsig[(size_t)token * (Hh * Ee) + tid];
    __syncthreads();

    // 512 outputs: e (4) x dd (128: K 0-63, V 64-127); 2 per thread
    #pragma unroll
    for (int r = 0; r < 2; r++) {
        int o = tid + r * 256;
        int e = o >> 7, dd = o & 127;
        int base = (dd < 64) ? 0 : 512;
        int d2 = dd & 63;
        float s = 0.f;
        #pragma unroll
        for (int h = 0; h < Hh; h++)
            s += g[h * Ee + e] * kv[base + h * 64 + d2];
        float* dst = (dd < 64) ? d_gK : d_gV;
        dst[((size_t)(n * Ee + e) * Tt + t) * 64 + d2] = s;
    }
    if (tid < Ee) {
        float sa = 0.f;
        #pragma unroll
        for (int h = 0; h < Hh; h++) sa += g[h * Ee + tid];
        d_A[(size_t)(n * Ee + tid) * Tt + t] = 1.f - sa;
    }
}

// ---------------------------------------------------------------------------
// Scan: L-strided recurrence rec[t] = A[t]*rec[t-L] + gated[t].
// ---------------------------------------------------------------------------
__global__ void __launch_bounds__(128) scan_kernel(const float* __restrict__ initK,
                                                   const float* __restrict__ initV) {
    const int b = blockIdx.x;             // Nn*Ee*Ll = 256 blocks
    const int l = b % Ll;
    const int e = (b / Ll) % Ee;
    const int n = b / (Ll * Ee);
    const int d = threadIdx.x;
    const bool isK = d < 64;
    const int dd = isK ? d : d - 64;
    const float* init = isK ? initK : initV;
    const float* gsrc = isK ? d_gK : d_gV;
    float* rec = isK ? d_recK : d_recV;
    const int ne = n * Ee + e;
    float y = init[(e * Ll + l) * 64 + dd];
    rec[(ne * REC_T + l) * 64 + dd] = y;
    const float* Arow = d_A + ne * Tt;
    const float* grow = gsrc + ne * Tt * 64;
    float* rrow = rec + (ne * REC_T + Ll) * 64;
    #pragma unroll 8
    for (int m = 0; m < M_CH; m++) {
        int t = m * Ll + l;
        y = Arow[t] * y + grow[t * 64 + dd];
        rrow[t * 64 + dd] = y;
    }
}

// ---------------------------------------------------------------------------
// Attention: one block per 2 tokens (same n; Tt even so no cross-n blocks).
// 8 heads x 2 tokens share a 132-row window (E=4 experts x 33 positions).
// 256 threads. Epilogue writes Y as bf16 hi/lo planes.
// ---------------------------------------------------------------------------
#define TB 2
#define WRR (Ee*(Ll+TB-1))             // 132 window rows
#define ATT_SMEM ((TB*512 + 2*WRR*65 + TB*8*128) * 4)

__global__ void __launch_bounds__(256) attn_kernel() {
    extern __shared__ float smem[];
    float* qs = smem;                      // TB*512
    float* Ks = qs + TB * 512;             // WRR*65 (padded rows)
    float* Vs = Ks + WRR * 65;             // WRR*65
    float* sc = Vs + WRR * 65;             // TB*8*128
    const int token0 = blockIdx.x * TB;
    const int n = token0 / Tt, t0 = token0 % Tt;
    const int tid = threadIdx.x;

    #pragma unroll
    for (int i = 0; i < TB * 2; i++)
        qs[tid + i * 256] = d_Q[(size_t)token0 * 512 + tid + i * 256];

    for (int i = tid; i < WRR * 64; i += 256) {
        int j = i >> 6, dd = i & 63;
        int e = j / (Ll + TB - 1);
        int ii = j - e * (Ll + TB - 1);
        int pos = t0 + ii + 1;                      // <= 2079 < REC_T
        int off = ((n * Ee + e) * REC_T + pos) * 64 + dd;
        Ks[j * 65 + dd] = d_recK[off];
        Vs[j * 65 + dd] = d_recV[off];
    }
    __syncthreads();

    // scores: TB x 8 heads x 128 slots = 2048 tasks
    #pragma unroll
    for (int r = 0; r < 8; r++) {
        int task = tid + r * 256;
        int tt = task >> 10;
        int h = (task >> 7) & 7;
        int j = task & 127;
        int e = j >> 5, l = j & 31;
        const float* qrow = qs + tt * 512 + h * 64;
        const float* krow = Ks + (e * (Ll + TB - 1) + tt + l) * 65;
        float s = 0.f;
        #pragma unroll
        for (int d = 0; d < 64; d++) s += qrow[d] * krow[d];
        sc[(tt * 8 + h) * 128 + j] = s * 0.125f;    // 1/sqrt(64)
    }
    __syncthreads();

    // softmax over 128 slots: 8 warps, each handles 2 of 16 (tt,h) rows
    {
        int w = tid >> 5, lane = tid & 31;
        #pragma unroll
        for (int p = 0; p < 2; p++) {
            float* rw = sc + (w * 2 + p) * 128;
            float v0 = rw[lane], v1 = rw[lane + 32];
            float v2 = rw[lane + 64], v3 = rw[lane + 96];
            float mx = fmaxf(fmaxf(v0, v1), fmaxf(v2, v3));
            #pragma unroll
            for (int o = 16; o; o >>= 1) mx = fmaxf(mx, __shfl_xor_sync(0xffffffffu, mx, o));
            float e0 = expf(v0 - mx), e1 = expf(v1 - mx);
            float e2 = expf(v2 - mx), e3 = expf(v3 - mx);
            float ssum = e0 + e1 + e2 + e3;
            #pragma unroll
            for (int o = 16; o; o >>= 1) ssum += __shfl_xor_sync(0xffffffffu, ssum, o);
            float inv = 1.f / ssum;
            rw[lane]      = e0 * inv;
            rw[lane + 32] = e1 * inv;
            rw[lane + 64] = e2 * inv;
            rw[lane + 96] = e3 * inv;
        }
    }
    __syncthreads();

    // output: TB x 8 heads x 64 dims = 1024 outputs, split to bf16 hi/lo
    #pragma unroll
    for (int r = 0; r < TB * 2; r++) {
        int o = tid + r * 256;
        int tt = o >> 9;
        int rem = o & 511;
        int h = rem >> 6, dd = rem & 63;
        const float* arow = sc + (tt * 8 + h) * 128;
        float acc = 0.f;
        #pragma unroll 4
        for (int j = 0; j < 128; j++) {
            int e = j >> 5, l = j & 31;
            acc += arow[j] * Vs[(e * (Ll + TB - 1) + tt + l) * 65 + dd];
        }
        bf16 hp, lp;
        split_bf(acc, hp, lp);
        d_Yh[(size_t)(token0 + tt) * 512 + rem] = hp;
        d_Yl[(size_t)(token0 + tt) * 512 + rem] = lp;
    }
}

// ---------------------------------------------------------------------------
extern "C" void kernel_launch(void* const* d_in, const int* in_sizes, int n_in,
                              void* d_out, int out_size) {
    const float* X  = (const float*)d_in[0];
    const float* wG = (const float*)d_in[1];
    const float* bG = (const float*)d_in[2];
    const float* wK = (const float*)d_in[3];
    const float* wV = (const float*)d_in[4];
    const float* wQ = (const float*)d_in[5];
    const float* wO = (const float*)d_in[6];
    const float* iK = (const float*)d_in[7];
    const float* iV = (const float*)d_in[8];
    float* out = (float*)d_out;

    cudaFuncSetAttribute(gemm_kvq, cudaFuncAttributeMaxDynamicSharedMemorySize, GSMB);
    cudaFuncSetAttribute(gemm_out, cudaFuncAttributeMaxDynamicSharedMemorySize, GSMB);
    cudaFuncSetAttribute(g_kernel, cudaFuncAttributeMaxDynamicSharedMemorySize, G_SMEM);
    cudaFuncSetAttribute(attn_kernel, cudaFuncAttributeMaxDynamicSharedMemorySize, ATT_SMEM);

    // One-shot operand preparation (splits + transpose)
    split_w<<<dim3(512, 3), 256>>>(wK, wV, wQ);
    transpose_wo<<<dim3(32, 16), dim3(32, 8)>>>(wO);
    g_kernel<<<NT / GTOK, 256, G_SMEM>>>(X, wG, bG);  // also emits d_Xh / d_Xl

    // K/V/Q projections on pre-split bf16 planes, fused on grid.z
    gemm_kvq<<<dim3(4, 32, 3), 256, GSMB>>>();

    gated_kernel<<<NT, 256>>>();
    scan_kernel<<<Nn * Ee * Ll, 128>>>(iK, iV);

    attn_kernel<<<NT / TB, 256, ATT_SMEM>>>();

    // Output: out = Y * wO = Y * (wOT)^T
    gemm_out<<<dim3(8, 32), 256, GSMB>>>(out);
}